// round 1
// baseline (speedup 1.0000x reference)
#include <cuda_runtime.h>
#include <mma.h>
#include <math.h>

using namespace nvcuda;

#define BB  16
#define CC  128
#define PP  48
#define NN  2304
#define CQ  16          // C/8
#define BCN (BB*CC*NN)  // 4718592

// ---------------- scratch (device globals; no allocation allowed) ----------------
__device__ float g_mean[CC], g_rstd[CC];
__device__ float g_xn[BCN];
__device__ float g_t1[BCN];
__device__ float g_feat[BCN];
__device__ float g_v[BCN];                   // (B, C, N)
__device__ float g_Vout[BCN];                // (B, N, C)  attention output, transposed
__device__ float g_T[BCN];
__device__ float g_fr[BCN];
__device__ float g_q[BB*NN*CQ];              // (B, N, 16)
__device__ float g_k[BB*NN*CQ];              // (B, N, 16)
__device__ float g_energy[(size_t)BB*NN*NN]; // (B, N, N) ~340MB

// ---------------- batchnorm ----------------
__global__ void bn_stats_kernel(const float* __restrict__ x) {
    int c = blockIdx.x;
    float s1 = 0.f, s2 = 0.f;
    for (int idx = threadIdx.x; idx < BB*NN; idx += 256) {
        int b = idx / NN, n = idx - b*NN;
        float v = x[((size_t)b*CC + c)*NN + n];
        s1 += v; s2 += v*v;
    }
    __shared__ float r1[256], r2[256];
    r1[threadIdx.x] = s1; r2[threadIdx.x] = s2;
    __syncthreads();
    for (int s = 128; s > 0; s >>= 1) {
        if (threadIdx.x < s) { r1[threadIdx.x] += r1[threadIdx.x+s]; r2[threadIdx.x] += r2[threadIdx.x+s]; }
        __syncthreads();
    }
    if (threadIdx.x == 0) {
        const float inv = 1.f / (float)(BB*NN);
        float m = r1[0] * inv;
        float var = r2[0] * inv - m*m;
        g_mean[c] = m;
        g_rstd[c] = rsqrtf(var + 1e-5f);
    }
}

__global__ void bn_apply_kernel(const float* __restrict__ x, const float* __restrict__ gam,
                                const float* __restrict__ bet, float* __restrict__ y) {
    int idx = blockIdx.x*256 + threadIdx.x;
    int c = (idx / NN) % CC;
    y[idx] = (x[idx] - g_mean[c]) * g_rstd[c] * gam[c] + bet[c];
}

// ---------------- TF32 wmma GEMM:  C[m,n] = op( sum_k A[m,k]*W[n,k] + bias[n] ) ----------------
// grid: (Nn/128, M/128, batch), 256 threads (8 warps as 2x4)
#define GBM 128
#define GBN 128
#define GBK 16
#define GLD 20

template<bool RELU>
__global__ __launch_bounds__(256) void gemm_abt_kernel(
    const float* __restrict__ A, const float* __restrict__ W,
    const float* __restrict__ bias, float* __restrict__ Cc,
    int M, int Nn, int K, size_t sA, size_t sW, size_t sC)
{
    __shared__ float As[GBM*GLD];
    __shared__ float Ws[GBN*GLD];
    const int tid  = threadIdx.x;
    const int warp = tid >> 5, lane = tid & 31;
    const int wm = warp & 1;   // 2 warp-rows of 64
    const int wn = warp >> 1;  // 4 warp-cols of 32

    A  += (size_t)blockIdx.z*sA + (size_t)blockIdx.y*GBM*K;
    W  += (size_t)blockIdx.z*sW + (size_t)blockIdx.x*GBN*K;
    Cc += (size_t)blockIdx.z*sC + (size_t)blockIdx.y*GBM*Nn + (size_t)blockIdx.x*GBN;

    wmma::fragment<wmma::accumulator,16,16,8,float> acc[4][2];
    #pragma unroll
    for (int i = 0; i < 4; i++)
        #pragma unroll
        for (int j = 0; j < 2; j++)
            wmma::fill_fragment(acc[i][j], 0.f);

    for (int k0 = 0; k0 < K; k0 += GBK) {
        #pragma unroll
        for (int i = 0; i < 2; i++) {
            int idx = tid + i*256;        // 0..511
            int row = idx >> 2;           // 0..127
            int c4  = (idx & 3) << 2;     // 0,4,8,12
            float4 va = *reinterpret_cast<const float4*>(A + (size_t)row*K + k0 + c4);
            float4 vb = *reinterpret_cast<const float4*>(W + (size_t)row*K + k0 + c4);
            float* da = As + row*GLD + c4;
            float* db = Ws + row*GLD + c4;
            da[0] = wmma::__float_to_tf32(va.x); da[1] = wmma::__float_to_tf32(va.y);
            da[2] = wmma::__float_to_tf32(va.z); da[3] = wmma::__float_to_tf32(va.w);
            db[0] = wmma::__float_to_tf32(vb.x); db[1] = wmma::__float_to_tf32(vb.y);
            db[2] = wmma::__float_to_tf32(vb.z); db[3] = wmma::__float_to_tf32(vb.w);
        }
        __syncthreads();
        #pragma unroll
        for (int kk = 0; kk < 2; kk++) {
            wmma::fragment<wmma::matrix_a,16,16,8,wmma::precision::tf32,wmma::row_major> af[4];
            wmma::fragment<wmma::matrix_b,16,16,8,wmma::precision::tf32,wmma::col_major> bf[2];
            #pragma unroll
            for (int i = 0; i < 4; i++)
                wmma::load_matrix_sync(af[i], As + (wm*64 + i*16)*GLD + kk*8, GLD);
            #pragma unroll
            for (int j = 0; j < 2; j++)
                wmma::load_matrix_sync(bf[j], Ws + (wn*32 + j*16)*GLD + kk*8, GLD);
            #pragma unroll
            for (int i = 0; i < 4; i++)
                #pragma unroll
                for (int j = 0; j < 2; j++)
                    wmma::mma_sync(acc[i][j], af[i], bf[j], acc[i][j]);
        }
        __syncthreads();
    }

    // epilogue: stage 16x16 fragments through shared (reuse As), add bias / relu
    float* st = As + warp*256;
    #pragma unroll
    for (int i = 0; i < 4; i++) {
        #pragma unroll
        for (int j = 0; j < 2; j++) {
            wmma::store_matrix_sync(st, acc[i][j], 16, wmma::mem_row_major);
            __syncwarp();
            int gr0 = wm*64 + i*16;
            int gc0 = wn*32 + j*16;
            #pragma unroll
            for (int e = 0; e < 8; e++) {
                int li = lane*8 + e;
                int r = li >> 4, c2 = li & 15;
                float v = st[li];
                if (bias) v += bias[blockIdx.x*GBN + gc0 + c2];
                if (RELU) v = fmaxf(v, 0.f);
                Cc[(size_t)(gr0 + r)*Nn + gc0 + c2] = v;
            }
            __syncwarp();
        }
    }
}

// ---------------- conv1x1 (channel mix), optional concat input, optional transposed output ----------
// X1: (B, Cin1, N).  X2 (optional): (B, N, Cin2).  out: outT ? (B,N,Cout) : (B,Cout,N)
// grid: (N/32, B), block (32, 8)
__global__ __launch_bounds__(256) void conv1x1_kernel(
    const float* __restrict__ X1, const float* __restrict__ X2,
    const float* __restrict__ W, const float* __restrict__ bias,
    float* __restrict__ out, int Cin1, int Cin2, int Cout, int outT)
{
    __shared__ float s1[CC*33];
    __shared__ float s2[CC*33];
    const int b  = blockIdx.y;
    const int n0 = blockIdx.x * 32;
    const int tid = threadIdx.y*32 + threadIdx.x;

    for (int idx = tid; idx < Cin1*32; idx += 256) {
        int c = idx >> 5, n = idx & 31;
        s1[c*33 + n] = X1[((size_t)b*Cin1 + c)*NN + n0 + n];
    }
    if (X2) {
        for (int idx = tid; idx < 32*Cin2; idx += 256) {
            int n = idx >> 7, c = idx & 127;   // Cin2 == 128
            s2[c*33 + n] = X2[((size_t)b*NN + n0 + n)*(size_t)Cin2 + c];
        }
    }
    __syncthreads();

    const int nx = threadIdx.x, ty = threadIdx.y;
    const int Ct = Cin1 + Cin2;
    for (int ob = 0; ob < Cout; ob += 32) {
        const int nacc = (Cout - ob) >= 32 ? 4 : ((Cout - ob + 7) >> 3);
        float acc[4];
        #pragma unroll
        for (int u = 0; u < 4; u++) acc[u] = (u < nacc) ? bias[ob + ty + 8*u] : 0.f;
        for (int c = 0; c < Cin1; c++) {
            float xv = s1[c*33 + nx];
            #pragma unroll
            for (int u = 0; u < 4; u++)
                if (u < nacc) acc[u] += W[(size_t)(ob + ty + 8*u)*Ct + c] * xv;
        }
        if (X2) {
            for (int c = 0; c < Cin2; c++) {
                float xv = s2[c*33 + nx];
                #pragma unroll
                for (int u = 0; u < 4; u++)
                    if (u < nacc) acc[u] += W[(size_t)(ob + ty + 8*u)*Ct + Cin1 + c] * xv;
            }
        }
        #pragma unroll
        for (int u = 0; u < 4; u++) if (u < nacc) {
            int o = ob + ty + 8*u;
            if (outT) out[((size_t)b*NN + n0 + nx)*(size_t)Cout + o] = acc[u];
            else      out[((size_t)b*Cout + o)*(size_t)NN + n0 + nx] = acc[u];
        }
    }
}

// ---------------- row softmax over last dim, with pre-scale ----------------
__global__ void softmax_kernel(float* __restrict__ E, float scale) {
    float* p = E + (size_t)blockIdx.x * NN;
    const int t = threadIdx.x;
    float r[9];
    float mx = -1e30f;
    #pragma unroll
    for (int i = 0; i < 9; i++) { r[i] = p[t + i*256] * scale; mx = fmaxf(mx, r[i]); }
    __shared__ float red[256];
    red[t] = mx; __syncthreads();
    for (int s = 128; s > 0; s >>= 1) { if (t < s) red[t] = fmaxf(red[t], red[t+s]); __syncthreads(); }
    mx = red[0];
    __syncthreads();
    float sum = 0.f;
    #pragma unroll
    for (int i = 0; i < 9; i++) { r[i] = expf(r[i] - mx); sum += r[i]; }
    red[t] = sum; __syncthreads();
    for (int s = 128; s > 0; s >>= 1) { if (t < s) red[t] += red[t+s]; __syncthreads(); }
    const float inv = 1.f / red[0];
    #pragma unroll
    for (int i = 0; i < 9; i++) p[t + i*256] = r[i] * inv;
}

// ---------------- launch ----------------
extern "C" void kernel_launch(void* const* d_in, const int* in_sizes, int n_in,
                              void* d_out, int out_size) {
    (void)in_sizes; (void)n_in; (void)out_size;
    const float* front_x = (const float*)d_in[0];
    const float* bn1_g   = (const float*)d_in[1];
    const float* bn1_b   = (const float*)d_in[2];
    const float* tm1_w1  = (const float*)d_in[3];
    const float* tm1_b1  = (const float*)d_in[4];
    const float* tm1_w2  = (const float*)d_in[5];
    const float* tm1_b2  = (const float*)d_in[6];
    const float* q_w     = (const float*)d_in[7];
    const float* q_b     = (const float*)d_in[8];
    const float* k_w     = (const float*)d_in[9];
    const float* k_b     = (const float*)d_in[10];
    const float* v_w     = (const float*)d_in[11];
    const float* v_b     = (const float*)d_in[12];
    const float* m1_w    = (const float*)d_in[13];
    const float* m1_b    = (const float*)d_in[14];
    const float* bn2_g   = (const float*)d_in[15];
    const float* bn2_b   = (const float*)d_in[16];
    const float* tm2_w1  = (const float*)d_in[17];
    const float* tm2_b1  = (const float*)d_in[18];
    const float* tm2_w2  = (const float*)d_in[19];
    const float* tm2_b2  = (const float*)d_in[20];
    const float* m2_w    = (const float*)d_in[21];
    const float* m2_b    = (const float*)d_in[22];
    float* out = (float*)d_out;

    float *p_xn, *p_t1, *p_feat, *p_v, *p_V, *p_T, *p_fr, *p_q, *p_k, *p_E;
    cudaGetSymbolAddress((void**)&p_xn,  g_xn);
    cudaGetSymbolAddress((void**)&p_t1,  g_t1);
    cudaGetSymbolAddress((void**)&p_feat,g_feat);
    cudaGetSymbolAddress((void**)&p_v,   g_v);
    cudaGetSymbolAddress((void**)&p_V,   g_Vout);
    cudaGetSymbolAddress((void**)&p_T,   g_T);
    cudaGetSymbolAddress((void**)&p_fr,  g_fr);
    cudaGetSymbolAddress((void**)&p_q,   g_q);
    cudaGetSymbolAddress((void**)&p_k,   g_k);
    cudaGetSymbolAddress((void**)&p_E,   g_energy);

    const dim3 gTM(NN/128, (BB*CC)/128, 1);
    const dim3 gE(NN/128, NN/128, BB);
    const dim3 gV(CC/128, NN/128, BB);
    const dim3 cgrid(NN/32, BB), cblk(32, 8);

    // stage 1: bn1 + tm1
    bn_stats_kernel<<<CC, 256>>>(front_x);
    bn_apply_kernel<<<BCN/256, 256>>>(front_x, bn1_g, bn1_b, p_xn);
    gemm_abt_kernel<true><<<gTM, 256>>>(p_xn, tm1_w1, tm1_b1, p_t1, BB*CC, NN, NN, 0, 0, 0);
    gemm_abt_kernel<true><<<gTM, 256>>>(p_t1, tm1_w2, tm1_b2, p_feat, BB*CC, NN, NN, 0, 0, 0);

    // q, k (stored transposed (B,N,16)), v (B,C,N)
    conv1x1_kernel<<<cgrid, cblk>>>(p_feat, nullptr, q_w, q_b, p_q, CC, 0, CQ, 1);
    conv1x1_kernel<<<cgrid, cblk>>>(p_feat, nullptr, k_w, k_b, p_k, CC, 0, CQ, 1);
    conv1x1_kernel<<<cgrid, cblk>>>(p_feat, nullptr, v_w, v_b, p_v, CC, 0, CC, 0);

    // attention: energy = Kt * Qt^T, softmax(scale), Vout = energy * v^T  (stored (B,N,C))
    gemm_abt_kernel<false><<<gE, 256>>>(p_k, p_q, nullptr, p_E, NN, NN, CQ,
                                        (size_t)NN*CQ, (size_t)NN*CQ, (size_t)NN*NN);
    softmax_kernel<<<BB*NN, 256>>>(p_E, 0.08838834764831845f);  // 1/sqrt(128)
    gemm_abt_kernel<false><<<gV, 256>>>(p_E, p_v, nullptr, p_V, NN, CC, NN,
                                        (size_t)NN*NN, (size_t)CC*NN, (size_t)NN*CC);

    // m1 on concat(features, V)
    conv1x1_kernel<<<cgrid, cblk>>>(p_feat, p_V, m1_w, m1_b, p_T, CC, CC, CC, 0);

    // stage 2: bn2 + tm2
    bn_stats_kernel<<<CC, 256>>>(p_T);
    bn_apply_kernel<<<BCN/256, 256>>>(p_T, bn2_g, bn2_b, p_xn);
    gemm_abt_kernel<true><<<gTM, 256>>>(p_xn, tm2_w1, tm2_b1, p_t1, BB*CC, NN, NN, 0, 0, 0);
    gemm_abt_kernel<true><<<gTM, 256>>>(p_t1, tm2_w2, tm2_b2, p_fr, BB*CC, NN, NN, 0, 0, 0);

    // m2 on concat(front_res, V) -> output
    conv1x1_kernel<<<cgrid, cblk>>>(p_fr, p_V, m2_w, m2_b, out, CC, CC, CC, 0);
}